// round 13
// baseline (speedup 1.0000x reference)
#include <cuda_runtime.h>
#include <cuda_bf16.h>
#include <math.h>

#define F 128
#define NHEADS 8
#define SCALE 0.25f            // 1/sqrt(16)
#define MAXN 50048
#define MAXE 640064
#define OFFM (MAXN*NHEADS)
#define PGRID 152               // persistent, 1 CTA/SM

// ---------------- device scratch (static: no allocations allowed) ----------
__device__ float g_q  [MAXN*F];
__device__ float g_v  [MAXN*F];
__device__ float g_Ein[MAXE*NHEADS];   // exp(logit) * att
__device__ float g_Eou[MAXE*NHEADS];
__device__ float g_Edg[MAXE*NHEADS];
__device__ float g_att[MAXE];
// per-node 32-float slot: [kind0 h0..7][kind1 h0..7][kind2 h0..7][pad 8]
__device__ float g_D  [MAXN*32];
__device__ float g_Di [MAXN*32];
__device__ float g_S  [OFFM];          // per (node,head) score sum

// ---------------- helpers ---------------------------------------------------
__device__ __forceinline__ unsigned smem_u32(const void* p) {
    return (unsigned)__cvta_generic_to_shared(p);
}
__device__ __forceinline__ unsigned pack_bf2(float flo, float fhi) {
    unsigned r;
    asm("cvt.rn.satfinite.bf16x2.f32 %0, %1, %2;" : "=r"(r) : "f"(fhi), "f"(flo));
    return r;
}
__device__ __forceinline__ void mma_bf16(float (&c)[4], const unsigned (&a)[4],
                                         const unsigned* b) {
    asm volatile("mma.sync.aligned.m16n8k16.row.col.f32.bf16.bf16.f32 "
        "{%0,%1,%2,%3}, {%4,%5,%6,%7}, {%8,%9}, {%0,%1,%2,%3};"
        : "+f"(c[0]), "+f"(c[1]), "+f"(c[2]), "+f"(c[3])
        : "r"(a[0]), "r"(a[1]), "r"(a[2]), "r"(a[3]), "r"(b[0]), "r"(b[1]));
}
__device__ __forceinline__ void ldsm_x4(unsigned (&r)[4], unsigned addr) {
    asm volatile("ldmatrix.sync.aligned.m8n8.x4.shared.b16 {%0,%1,%2,%3}, [%4];"
        : "=r"(r[0]), "=r"(r[1]), "=r"(r[2]), "=r"(r[3]) : "r"(addr));
}
// vectorized global reduction: 4 consecutive f32 adds, one L2 op (16B aligned)
__device__ __forceinline__ void red4(float* p, float a, float b, float c, float d) {
    asm volatile("red.global.add.v4.f32 [%0], {%1,%2,%3,%4};"
        :: "l"(p), "f"(a), "f"(b), "f"(c), "f"(d) : "memory");
}

#define SAW 136
#define TB  (128*SAW*2)
#define KPW 132

template<int NT, bool SCALED>
__device__ __forceinline__ void load_conv(const float* __restrict__ src, int row0, int nrows,
                                          __nv_bfloat16* aHi, __nv_bfloat16* aLo,
                                          int tid, const float* __restrict__ scl) {
    for (int g = tid; g < 2048; g += NT) {
        int row = g >> 4, c8 = (g & 15) << 3;
        float fs[8] = {0.f, 0.f, 0.f, 0.f, 0.f, 0.f, 0.f, 0.f};
        int gr = row0 + row;
        if (gr < nrows) {
            const float4* p = (const float4*)(src + (size_t)gr * 128 + c8);
            float4 f0 = p[0], f1 = p[1];
            fs[0] = f0.x; fs[1] = f0.y; fs[2] = f0.z; fs[3] = f0.w;
            fs[4] = f1.x; fs[5] = f1.y; fs[6] = f1.z; fs[7] = f1.w;
            if (SCALED) {
                float sc = scl[gr * NHEADS + (c8 >> 4)];
#pragma unroll
                for (int j = 0; j < 8; j++) fs[j] *= sc;
            }
        }
        unsigned hi[4], lo[4];
#pragma unroll
        for (int j = 0; j < 4; j++) {
            unsigned h = pack_bf2(fs[2 * j], fs[2 * j + 1]);
            float h0f = __uint_as_float(h << 16);
            float h1f = __uint_as_float(h & 0xFFFF0000u);
            hi[j] = h;
            lo[j] = pack_bf2(fs[2 * j] - h0f, fs[2 * j + 1] - h1f);
        }
        *(uint4*)(aHi + row * SAW + c8) = make_uint4(hi[0], hi[1], hi[2], hi[3]);
        *(uint4*)(aLo + row * SAW + c8) = make_uint4(lo[0], lo[1], lo[2], lo[3]);
    }
}

// one warp's 16x64 share of C = A[128x128] @ W^T[128x128], split bf16, ldmatrix
__device__ __forceinline__ void mma_tile(const __nv_bfloat16* aH, const __nv_bfloat16* aL,
                                         const __nv_bfloat16* wH, const __nv_bfloat16* wL,
                                         int lane, int wr, int wc, float (&acc)[8][4]) {
#pragma unroll
    for (int nt = 0; nt < 8; nt++)
#pragma unroll
        for (int c = 0; c < 4; c++) acc[nt][c] = 0.f;
    unsigned aoff = (unsigned)(((wr + (lane & 7) + ((lane >> 3) & 1) * 8) * SAW
                                + (lane >> 4) * 8) * 2);
    unsigned aHb = smem_u32(aH) + aoff, aLb = smem_u32(aL) + aoff;
    unsigned boff = (unsigned)(((wc + (lane & 7) + (lane >> 4) * 8) * SAW
                                + ((lane >> 3) & 1) * 8) * 2);
    unsigned wHb = smem_u32(wH) + boff, wLb = smem_u32(wL) + boff;
#pragma unroll
    for (int ks = 0; ks < 8; ks++) {
        unsigned kb = (unsigned)(ks * 32);
        unsigned aHf[4], aLf[4];
        ldsm_x4(aHf, aHb + kb);
        ldsm_x4(aLf, aLb + kb);
#pragma unroll
        for (int np = 0; np < 4; np++) {
            unsigned bH[4], bL[4];
            unsigned nb = (unsigned)(np * 16 * SAW * 2) + kb;
            ldsm_x4(bH, wHb + nb);
            ldsm_x4(bL, wLb + nb);
            mma_bf16(acc[np * 2],     aHf, &bH[0]);
            mma_bf16(acc[np * 2],     aHf, &bL[0]);
            mma_bf16(acc[np * 2],     aLf, &bH[0]);
            mma_bf16(acc[np * 2 + 1], aHf, &bH[2]);
            mma_bf16(acc[np * 2 + 1], aHf, &bL[2]);
            mma_bf16(acc[np * 2 + 1], aLf, &bH[2]);
        }
    }
}

// ---------------- smem layouts (byte offsets) -------------------------------
#define K_WH 0
#define K_WL TB
#define K_AH (2*TB)
#define K_AL (3*TB)
#define K_KF (4*TB)
#define K_SB (K_KF + 128*KPW*4)
#define K_SMEM (K_SB + 512)
#define QV_WQH 0
#define QV_WQL TB
#define QV_WVH (2*TB)
#define QV_WVL (3*TB)
#define QV_AH  (4*TB)
#define QV_AL  (5*TB)
#define QV_SBQ (6*TB)
#define QV_SBV (QV_SBQ + 512)
#define QV_SMEM (QV_SBV + 512)
#define O_WH 0
#define O_WL TB
#define O_AH (2*TB)
#define O_AL (3*TB)
#define O_SB (4*TB)
#define O_SMEM (O_SB + 512)

// ---------------- kernels ---------------------------------------------------

__global__ void __launch_bounds__(512, 1) qv_tc_kernel(const float* __restrict__ node_h,
        const float* __restrict__ Wq, const float* __restrict__ bq,
        const float* __restrict__ Wv, const float* __restrict__ bv, int N) {
    extern __shared__ char sm[];
    int tid = threadIdx.x, wid = tid >> 5, lane = tid & 31;
    __nv_bfloat16* WqH = (__nv_bfloat16*)(sm + QV_WQH);
    __nv_bfloat16* WqL = (__nv_bfloat16*)(sm + QV_WQL);
    __nv_bfloat16* WvH = (__nv_bfloat16*)(sm + QV_WVH);
    __nv_bfloat16* WvL = (__nv_bfloat16*)(sm + QV_WVL);
    __nv_bfloat16* AH  = (__nv_bfloat16*)(sm + QV_AH);
    __nv_bfloat16* AL  = (__nv_bfloat16*)(sm + QV_AL);
    float* sBq = (float*)(sm + QV_SBQ);
    float* sBv = (float*)(sm + QV_SBV);
    load_conv<512, false>(Wq, 0, 128, WqH, WqL, tid, nullptr);
    load_conv<512, false>(Wv, 0, 128, WvH, WvL, tid, nullptr);
    if (tid < 128) { sBq[tid] = bq[tid]; sBv[tid] = bv[tid]; }
    __syncthreads();
    int wr = (wid >> 1) << 4, wc = (wid & 1) << 6;
    int qp = (lane & 3) * 2;
    int ntiles = (N + 127) >> 7;
    for (int tile = blockIdx.x; tile < ntiles; tile += gridDim.x) {
        int row0 = tile << 7;
        load_conv<512, false>(node_h, row0, N, AH, AL, tid, nullptr);
        __syncthreads();
        float acc[8][4];
        mma_tile(AH, AL, WqH, WqL, lane, wr, wc, acc);
        {
            int r = wr + (lane >> 2);
            int gr0 = row0 + r, gr1 = gr0 + 8;
#pragma unroll
            for (int nt = 0; nt < 8; nt++) {
                int col = wc + nt * 8 + qp;
                if (gr0 < N) *(float2*)(g_q + (size_t)gr0 * 128 + col) =
                    make_float2(acc[nt][0] + sBq[col], acc[nt][1] + sBq[col + 1]);
                if (gr1 < N) *(float2*)(g_q + (size_t)gr1 * 128 + col) =
                    make_float2(acc[nt][2] + sBq[col], acc[nt][3] + sBq[col + 1]);
            }
        }
        mma_tile(AH, AL, WvH, WvL, lane, wr, wc, acc);
        {
            int r = wr + (lane >> 2);
            int gr0 = row0 + r, gr1 = gr0 + 8;
#pragma unroll
            for (int nt = 0; nt < 8; nt++) {
                int col = wc + nt * 8 + qp;
                if (gr0 < N) *(float2*)(g_v + (size_t)gr0 * 128 + col) =
                    make_float2(acc[nt][0] + sBv[col], acc[nt][1] + sBv[col + 1]);
                if (gr1 < N) *(float2*)(g_v + (size_t)gr1 * 128 + col) =
                    make_float2(acc[nt][2] + sBv[col], acc[nt][3] + sBv[col + 1]);
            }
        }
        __syncthreads();
    }
}

__global__ void __launch_bounds__(512, 1) k_logits_tc_kernel(const float* __restrict__ edge_h,
        const float* __restrict__ Wk, const float* __restrict__ bk,
        const int* __restrict__ src, const int* __restrict__ dst, int E) {
    extern __shared__ char sm[];
    int tid = threadIdx.x, wid = tid >> 5, lane = tid & 31;
    __nv_bfloat16* WH = (__nv_bfloat16*)(sm + K_WH);
    __nv_bfloat16* WL = (__nv_bfloat16*)(sm + K_WL);
    __nv_bfloat16* AH = (__nv_bfloat16*)(sm + K_AH);
    __nv_bfloat16* AL = (__nv_bfloat16*)(sm + K_AL);
    float* kf = (float*)(sm + K_KF);
    float* sB = (float*)(sm + K_SB);
    load_conv<512, false>(Wk, 0, 128, WH, WL, tid, nullptr);
    if (tid < 128) sB[tid] = bk[tid];
    __syncthreads();
    int wr = (wid >> 1) << 4, wc = (wid & 1) << 6;
    int qp = (lane & 3) * 2;
    int et  = tid >> 1;          // epilogue: edge-in-tile (tid<256)
    int h0  = (tid & 1) * 4;     // head quad base
    int ntiles = (E + 127) >> 7;
    for (int tile = blockIdx.x; tile < ntiles; tile += gridDim.x) {
        int row0 = tile << 7;
        // overlaps previous tile's epilogue (kf ≠ AH/AL; MMA reads fenced earlier)
        load_conv<512, false>(edge_h, row0, E, AH, AL, tid, nullptr);
        int e = row0 + et;
        bool ev = (tid < 256) && (e < E);
        int s0 = 0, d0 = 0;
        float att = 0.f;
        if (ev) { s0 = __ldg(src + e); d0 = __ldg(dst + e); att = __ldg(g_att + e); }
        __syncthreads();
        float acc[8][4];
        mma_tile(AH, AL, WH, WL, lane, wr, wc, acc);
        {
            int r = wr + (lane >> 2);
#pragma unroll
            for (int nt = 0; nt < 8; nt++) {
                int col = wc + nt * 8 + qp;
                *(float2*)(kf + r * KPW + col) =
                    make_float2(acc[nt][0] + sB[col], acc[nt][1] + sB[col + 1]);
                *(float2*)(kf + (r + 8) * KPW + col) =
                    make_float2(acc[nt][2] + sB[col], acc[nt][3] + sB[col + 1]);
            }
        }
        __syncthreads();
        // ---- epilogue: 256 (edge, head-quad) items on threads 0..255;
        //      warps 8..15 run ahead into the next tile's load_conv.
        if (ev) {
            float einv[4], eouv[4], edgv[4];
#pragma unroll
            for (int hh = 0; hh < 4; hh++) {
                int head = h0 + hh;
                const float4* ps = (const float4*)(g_q + (size_t)s0 * 128 + head * 16);
                const float4* pd = (const float4*)(g_q + (size_t)d0 * 128 + head * 16);
                const float4* kk = (const float4*)(kf + et * KPW + head * 16);
                float im = 0.f, om = 0.f, dg = 0.f;
#pragma unroll
                for (int j = 0; j < 4; j++) {
                    float4 a = ps[j], b = pd[j], c = kk[j];
                    im += a.x*c.x + a.y*c.y + a.z*c.z + a.w*c.w;
                    om += b.x*c.x + b.y*c.y + b.z*c.z + b.w*c.w;
                    dg += a.x*b.x + a.y*b.y + a.z*b.z + a.w*b.w;
                }
                einv[hh] = __expf(im * SCALE);
                eouv[hh] = __expf(om * SCALE);
                edgv[hh] = __expf(dg * SCALE);
            }
            size_t o = (size_t)e * NHEADS + h0;
            *(float4*)&g_Ein[o] = make_float4(einv[0]*att, einv[1]*att, einv[2]*att, einv[3]*att);
            *(float4*)&g_Eou[o] = make_float4(eouv[0]*att, eouv[1]*att, eouv[2]*att, eouv[3]*att);
            *(float4*)&g_Edg[o] = make_float4(edgv[0]*att, edgv[1]*att, edgv[2]*att, edgv[3]*att);
            float* db = g_D + (size_t)d0 * 32 + h0;
            red4(db,      einv[0], einv[1], einv[2], einv[3]);
            red4(db + 8,  eouv[0], eouv[1], eouv[2], eouv[3]);
            red4(db + 16, edgv[0], edgv[1], edgv[2], edgv[3]);
        }
        // no trailing barrier
    }
}

__global__ void __launch_bounds__(512, 1) out_tc_kernel(const float* __restrict__ Wo,
        const float* __restrict__ bo, float* __restrict__ out, int N) {
    extern __shared__ char sm[];
    int tid = threadIdx.x, wid = tid >> 5, lane = tid & 31;
    __nv_bfloat16* WH = (__nv_bfloat16*)(sm + O_WH);
    __nv_bfloat16* WL = (__nv_bfloat16*)(sm + O_WL);
    __nv_bfloat16* AH = (__nv_bfloat16*)(sm + O_AH);
    __nv_bfloat16* AL = (__nv_bfloat16*)(sm + O_AL);
    float* sB = (float*)(sm + O_SB);
    load_conv<512, false>(Wo, 0, 128, WH, WL, tid, nullptr);
    if (tid < 128) sB[tid] = bo[tid];
    __syncthreads();
    int wr = (wid >> 1) << 4, wc = (wid & 1) << 6;
    int qp = (lane & 3) * 2;
    int ntiles = (N + 127) >> 7;
    for (int tile = blockIdx.x; tile < ntiles; tile += gridDim.x) {
        int row0 = tile << 7;
        load_conv<512, true>(g_v, row0, N, AH, AL, tid, g_S);
        __syncthreads();
        float acc[8][4];
        mma_tile(AH, AL, WH, WL, lane, wr, wc, acc);
        {
            int r = wr + (lane >> 2);
            int gr0 = row0 + r, gr1 = gr0 + 8;
#pragma unroll
            for (int nt = 0; nt < 8; nt++) {
                int col = wc + nt * 8 + qp;
                float x0 = acc[nt][0] + sB[col],   x1 = acc[nt][1] + sB[col + 1];
                float x2 = acc[nt][2] + sB[col],   x3 = acc[nt][3] + sB[col + 1];
                x0 = (x0 > 0.f) ? x0 : 0.1f * x0;  x1 = (x1 > 0.f) ? x1 : 0.1f * x1;
                x2 = (x2 > 0.f) ? x2 : 0.1f * x2;  x3 = (x3 > 0.f) ? x3 : 0.1f * x3;
                if (gr0 < N) *(float2*)(out + (size_t)gr0 * 128 + col) = make_float2(x0, x1);
                if (gr1 < N) *(float2*)(out + (size_t)gr1 * 128 + col) = make_float2(x2, x3);
            }
        }
        __syncthreads();
    }
}

__global__ void init_kernel(const float* __restrict__ dist,
                            const float* __restrict__ lam, int E, int N) {
    int t = blockIdx.x * blockDim.x + threadIdx.x;
    if (t < N * 32) g_D[t] = 0.f;
    if (t < N * NHEADS) g_S[t] = 0.f;
    if (t < E) g_att[t] = powf(dist[t], lam[0]);
}

// Di = 1/D on the 24 used floats of each 32-float node slot
__global__ void recip_kernel(int N) {
    int t = blockIdx.x * blockDim.x + threadIdx.x;
    if (t >= N * 6) return;
    int n = t / 6, j = t - n * 6;
    float4 d = *(float4*)&g_D[n * 32 + j * 4];
    *(float4*)&g_Di[n * 32 + j * 4] =
        make_float4((d.x != 0.f) ? 1.f / d.x : 0.f,
                    (d.y != 0.f) ? 1.f / d.y : 0.f,
                    (d.z != 0.f) ? 1.f / d.z : 0.f,
                    (d.w != 0.f) ? 1.f / d.w : 0.f);
}

// per (edge, head-quad): S[dst, quad] += E·Di  (one vec reduction)
__global__ void score_kernel(const int* __restrict__ dst, int E) {
    int t = blockIdx.x * blockDim.x + threadIdx.x;
    if (t >= E * 2) return;
    int e = t >> 1, h0 = (t & 1) * 4;
    int d = dst[e];
    size_t o = (size_t)e * NHEADS + h0;
    float4 E0 = *(float4*)&g_Ein[o];
    float4 E1 = *(float4*)&g_Eou[o];
    float4 E2 = *(float4*)&g_Edg[o];
    const float* di = g_Di + (size_t)d * 32 + h0;
    float4 D0 = *(float4*)(di);
    float4 D1 = *(float4*)(di + 8);
    float4 D2 = *(float4*)(di + 16);
    red4(&g_S[d * NHEADS + h0],
         E0.x * D0.x + E1.x * D1.x + E2.x * D2.x,
         E0.y * D0.y + E1.y * D1.y + E2.y * D2.y,
         E0.z * D0.z + E1.z * D1.z + E2.z * D2.z,
         E0.w * D0.w + E1.w * D1.w + E2.w * D2.w);
}

// ---------------- launch -----------------------------------------------------
extern "C" void kernel_launch(void* const* d_in, const int* in_sizes, int n_in,
                              void* d_out, int out_size) {
    const float* node_h   = (const float*)d_in[0];
    const float* edge_h   = (const float*)d_in[1];
    const float* distance = (const float*)d_in[2];
    const float* Wq = (const float*)d_in[3];  const float* bq = (const float*)d_in[4];
    const float* Wk = (const float*)d_in[5];  const float* bk = (const float*)d_in[6];
    const float* Wv = (const float*)d_in[7];  const float* bv = (const float*)d_in[8];
    const float* Wo = (const float*)d_in[9];  const float* bo = (const float*)d_in[10];
    const float* lam = (const float*)d_in[11];
    const int*   src = (const int*)d_in[12];
    const int*   dst = (const int*)d_in[13];

    int N = in_sizes[0] / F;
    int E = in_sizes[12];
    float* out = (float*)d_out;

    cudaFuncSetAttribute(qv_tc_kernel, cudaFuncAttributeMaxDynamicSharedMemorySize, QV_SMEM);
    cudaFuncSetAttribute(k_logits_tc_kernel, cudaFuncAttributeMaxDynamicSharedMemorySize, K_SMEM);
    cudaFuncSetAttribute(out_tc_kernel, cudaFuncAttributeMaxDynamicSharedMemorySize, O_SMEM);

    int ib = (N * 32 + 255) / 256;
    if ((E + 255) / 256 > ib) ib = (E + 255) / 256;
    init_kernel<<<ib, 256>>>(distance, lam, E, N);

    qv_tc_kernel<<<PGRID, 512, QV_SMEM>>>(node_h, Wq, bq, Wv, bv, N);

    k_logits_tc_kernel<<<PGRID, 512, K_SMEM>>>(edge_h, Wk, bk, src, dst, E);

    int rb = (N * 6 + 255) / 256;
    int sb = (E * 2 + 255) / 256;
    recip_kernel<<<rb, 256>>>(N);
    score_kernel<<<sb, 256>>>(dst, E);

    out_tc_kernel<<<PGRID, 512, O_SMEM>>>(Wo, bo, out, N);
}

// round 14
// speedup vs baseline: 1.3703x; 1.3703x over previous
#include <cuda_runtime.h>
#include <cuda_bf16.h>
#include <math.h>

#define F 128
#define NHEADS 8
#define SCALE 0.25f            // 1/sqrt(16)
#define MAXN 50048
#define MAXE 640064
#define OFFM (MAXN*NHEADS)
#define PGRID 152               // persistent, 1 CTA/SM

// ---------------- device scratch (static: no allocations allowed) ----------
__device__ float g_q  [MAXN*F];
__device__ float g_v  [MAXN*F];
__device__ float g_Ein[MAXE*NHEADS];
__device__ float g_Eou[MAXE*NHEADS];
__device__ float g_Edg[MAXE*NHEADS];
__device__ float g_att[MAXE];
__device__ float g_D  [3*OFFM];
__device__ float g_Di [3*OFFM];
__device__ float g_S  [OFFM];

// ---------------- helpers ---------------------------------------------------
// pack two floats to bf16x2 (first arg -> low half)
__device__ __forceinline__ unsigned pack_bf2(float flo, float fhi) {
    unsigned r;
    asm("cvt.rn.satfinite.bf16x2.f32 %0, %1, %2;" : "=r"(r) : "f"(fhi), "f"(flo));
    return r;
}

// warp mma: C[16x8] += A[16x16](bf16,row) * B[16x8](bf16,col), fp32 acc
__device__ __forceinline__ void mma_bf16(float (&c)[4], const unsigned (&a)[4],
                                         const unsigned (&b)[2]) {
    asm volatile("mma.sync.aligned.m16n8k16.row.col.f32.bf16.bf16.f32 "
        "{%0,%1,%2,%3}, {%4,%5,%6,%7}, {%8,%9}, {%0,%1,%2,%3};"
        : "+f"(c[0]), "+f"(c[1]), "+f"(c[2]), "+f"(c[3])
        : "r"(a[0]), "r"(a[1]), "r"(a[2]), "r"(a[3]), "r"(b[0]), "r"(b[1]));
}

// bf16 tile row stride (elements): 128 data + 8 pad -> conflict-free fragments
#define SAW 136
#define TB  (128*SAW*2)          // bytes per 128x128 bf16 tile (34816)
#define KPW 132                  // fp32 k-tile row stride (floats)

// convert a 128x128 fp32 block (rows row0.., zero-padded past nrows) into
// hi/lo bf16 split tiles in smem. scl: optional per-(row,head) scale.
template<int NT, bool SCALED>
__device__ __forceinline__ void load_conv(const float* __restrict__ src, int row0, int nrows,
                                          __nv_bfloat16* aHi, __nv_bfloat16* aLo,
                                          int tid, const float* __restrict__ scl) {
    for (int g = tid; g < 2048; g += NT) {
        int row = g >> 4, c8 = (g & 15) << 3;
        float fs[8] = {0.f, 0.f, 0.f, 0.f, 0.f, 0.f, 0.f, 0.f};
        int gr = row0 + row;
        if (gr < nrows) {
            const float4* p = (const float4*)(src + (size_t)gr * 128 + c8);
            float4 f0 = p[0], f1 = p[1];
            fs[0] = f0.x; fs[1] = f0.y; fs[2] = f0.z; fs[3] = f0.w;
            fs[4] = f1.x; fs[5] = f1.y; fs[6] = f1.z; fs[7] = f1.w;
            if (SCALED) {
                float sc = scl[gr * NHEADS + (c8 >> 4)];
#pragma unroll
                for (int j = 0; j < 8; j++) fs[j] *= sc;
            }
        }
        unsigned hi[4], lo[4];
#pragma unroll
        for (int j = 0; j < 4; j++) {
            unsigned h = pack_bf2(fs[2 * j], fs[2 * j + 1]);
            float h0f = __uint_as_float(h << 16);
            float h1f = __uint_as_float(h & 0xFFFF0000u);
            hi[j] = h;
            lo[j] = pack_bf2(fs[2 * j] - h0f, fs[2 * j + 1] - h1f);
        }
        *(uint4*)(aHi + row * SAW + c8) = make_uint4(hi[0], hi[1], hi[2], hi[3]);
        *(uint4*)(aLo + row * SAW + c8) = make_uint4(lo[0], lo[1], lo[2], lo[3]);
    }
}

// one warp's 16x64 share of C = A[128x128] @ W^T[128x128] with bf16 split.
// wr: warp row base (0..112), wc: warp col base (0 or 64).  (R8-validated)
__device__ __forceinline__ void mma_tile(const __nv_bfloat16* aH, const __nv_bfloat16* aL,
                                         const __nv_bfloat16* wH, const __nv_bfloat16* wL,
                                         int lane, int wr, int wc, float (&acc)[8][4]) {
    int qp = (lane & 3) * 2;
    int r0 = wr + (lane >> 2);
#pragma unroll
    for (int nt = 0; nt < 8; nt++)
#pragma unroll
        for (int c = 0; c < 4; c++) acc[nt][c] = 0.f;
#pragma unroll
    for (int ks = 0; ks < 8; ks++) {
        int kc = ks * 16 + qp;
        unsigned aHf[4], aLf[4];
        aHf[0] = *(const unsigned*)(aH + r0 * SAW + kc);
        aHf[1] = *(const unsigned*)(aH + (r0 + 8) * SAW + kc);
        aHf[2] = *(const unsigned*)(aH + r0 * SAW + kc + 8);
        aHf[3] = *(const unsigned*)(aH + (r0 + 8) * SAW + kc + 8);
        aLf[0] = *(const unsigned*)(aL + r0 * SAW + kc);
        aLf[1] = *(const unsigned*)(aL + (r0 + 8) * SAW + kc);
        aLf[2] = *(const unsigned*)(aL + r0 * SAW + kc + 8);
        aLf[3] = *(const unsigned*)(aL + (r0 + 8) * SAW + kc + 8);
#pragma unroll
        for (int nt = 0; nt < 8; nt++) {
            int n = wc + nt * 8 + (lane >> 2);
            unsigned bHf[2], bLf[2];
            bHf[0] = *(const unsigned*)(wH + n * SAW + kc);
            bHf[1] = *(const unsigned*)(wH + n * SAW + kc + 8);
            bLf[0] = *(const unsigned*)(wL + n * SAW + kc);
            bLf[1] = *(const unsigned*)(wL + n * SAW + kc + 8);
            mma_bf16(acc[nt], aHf, bHf);
            mma_bf16(acc[nt], aHf, bLf);
            mma_bf16(acc[nt], aLf, bHf);
        }
    }
}

// ---------------- smem layouts (byte offsets) -------------------------------
#define K_WH 0
#define K_WL TB
#define K_AH (2*TB)
#define K_AL (3*TB)
#define K_KF (4*TB)
#define K_SB (K_KF + 128*KPW*4)
#define K_SMEM (K_SB + 512)
#define QV_WQH 0
#define QV_WQL TB
#define QV_WVH (2*TB)
#define QV_WVL (3*TB)
#define QV_AH  (4*TB)
#define QV_AL  (5*TB)
#define QV_SBQ (6*TB)
#define QV_SBV (QV_SBQ + 512)
#define QV_SMEM (QV_SBV + 512)
#define O_WH 0
#define O_WL TB
#define O_AH (2*TB)
#define O_AL (3*TB)
#define O_SB (4*TB)
#define O_SMEM (O_SB + 512)

// ---------------- kernels ---------------------------------------------------

__global__ void __launch_bounds__(512, 1) qv_tc_kernel(const float* __restrict__ node_h,
        const float* __restrict__ Wq, const float* __restrict__ bq,
        const float* __restrict__ Wv, const float* __restrict__ bv, int N) {
    extern __shared__ char sm[];
    int tid = threadIdx.x, wid = tid >> 5, lane = tid & 31;
    __nv_bfloat16* WqH = (__nv_bfloat16*)(sm + QV_WQH);
    __nv_bfloat16* WqL = (__nv_bfloat16*)(sm + QV_WQL);
    __nv_bfloat16* WvH = (__nv_bfloat16*)(sm + QV_WVH);
    __nv_bfloat16* WvL = (__nv_bfloat16*)(sm + QV_WVL);
    __nv_bfloat16* AH  = (__nv_bfloat16*)(sm + QV_AH);
    __nv_bfloat16* AL  = (__nv_bfloat16*)(sm + QV_AL);
    float* sBq = (float*)(sm + QV_SBQ);
    float* sBv = (float*)(sm + QV_SBV);
    load_conv<512, false>(Wq, 0, 128, WqH, WqL, tid, nullptr);
    load_conv<512, false>(Wv, 0, 128, WvH, WvL, tid, nullptr);
    if (tid < 128) { sBq[tid] = bq[tid]; sBv[tid] = bv[tid]; }
    __syncthreads();
    int wr = (wid >> 1) << 4, wc = (wid & 1) << 6;
    int qp = (lane & 3) * 2;
    int ntiles = (N + 127) >> 7;
    for (int tile = blockIdx.x; tile < ntiles; tile += gridDim.x) {
        int row0 = tile << 7;
        load_conv<512, false>(node_h, row0, N, AH, AL, tid, nullptr);
        __syncthreads();
        float acc[8][4];
        // ---- q ----
        mma_tile(AH, AL, WqH, WqL, lane, wr, wc, acc);
        {
            int r = wr + (lane >> 2);
            int gr0 = row0 + r, gr1 = gr0 + 8;
#pragma unroll
            for (int nt = 0; nt < 8; nt++) {
                int col = wc + nt * 8 + qp;
                if (gr0 < N) *(float2*)(g_q + (size_t)gr0 * 128 + col) =
                    make_float2(acc[nt][0] + sBq[col], acc[nt][1] + sBq[col + 1]);
                if (gr1 < N) *(float2*)(g_q + (size_t)gr1 * 128 + col) =
                    make_float2(acc[nt][2] + sBq[col], acc[nt][3] + sBq[col + 1]);
            }
        }
        // ---- v ----
        mma_tile(AH, AL, WvH, WvL, lane, wr, wc, acc);
        {
            int r = wr + (lane >> 2);
            int gr0 = row0 + r, gr1 = gr0 + 8;
#pragma unroll
            for (int nt = 0; nt < 8; nt++) {
                int col = wc + nt * 8 + qp;
                if (gr0 < N) *(float2*)(g_v + (size_t)gr0 * 128 + col) =
                    make_float2(acc[nt][0] + sBv[col], acc[nt][1] + sBv[col + 1]);
                if (gr1 < N) *(float2*)(g_v + (size_t)gr1 * 128 + col) =
                    make_float2(acc[nt][2] + sBv[col], acc[nt][3] + sBv[col + 1]);
            }
        }
        __syncthreads();   // A reads done before next conversion
    }
}

__global__ void __launch_bounds__(512, 1) k_logits_tc_kernel(const float* __restrict__ edge_h,
        const float* __restrict__ Wk, const float* __restrict__ bk,
        const int* __restrict__ src, const int* __restrict__ dst, int E) {
    extern __shared__ char sm[];
    int tid = threadIdx.x, wid = tid >> 5, lane = tid & 31;
    __nv_bfloat16* WH = (__nv_bfloat16*)(sm + K_WH);
    __nv_bfloat16* WL = (__nv_bfloat16*)(sm + K_WL);
    __nv_bfloat16* AH = (__nv_bfloat16*)(sm + K_AH);
    __nv_bfloat16* AL = (__nv_bfloat16*)(sm + K_AL);
    float* kf = (float*)(sm + K_KF);
    float* sB = (float*)(sm + K_SB);
    load_conv<512, false>(Wk, 0, 128, WH, WL, tid, nullptr);
    if (tid < 128) sB[tid] = bk[tid];
    __syncthreads();
    int wr = (wid >> 1) << 4, wc = (wid & 1) << 6;
    int qp = (lane & 3) * 2;
    int et0 = tid >> 3, h = tid & 7;      // item0: edge-in-tile 0..63; item1: +64
    int ntiles = (E + 127) >> 7;
    for (int tile = blockIdx.x; tile < ntiles; tile += gridDim.x) {
        int row0 = tile << 7;
        // No barrier before this load_conv: MMA reads of AH/AL for the previous
        // tile completed before the previous kf-write barrier, and epilogue(t-1)
        // touches only kf/globals, never AH/AL -> this overlaps the epilogue.
        load_conv<512, false>(edge_h, row0, E, AH, AL, tid, nullptr);
        // preload epilogue indices; latency hides under the GEMM
        int e0 = row0 + et0, e1 = e0 + 64;
        bool v0 = e0 < E, v1 = e1 < E;
        int s0 = 0, d0 = 0, s1 = 0, d1 = 0;
        if (v0) { s0 = __ldg(src + e0); d0 = __ldg(dst + e0); }
        if (v1) { s1 = __ldg(src + e1); d1 = __ldg(dst + e1); }
        __syncthreads();
        float acc[8][4];
        mma_tile(AH, AL, WH, WL, lane, wr, wc, acc);
        // write k tile (+bias) into smem
        {
            int r = wr + (lane >> 2);
#pragma unroll
            for (int nt = 0; nt < 8; nt++) {
                int col = wc + nt * 8 + qp;
                *(float2*)(kf + r * KPW + col) =
                    make_float2(acc[nt][0] + sB[col], acc[nt][1] + sB[col + 1]);
                *(float2*)(kf + (r + 8) * KPW + col) =
                    make_float2(acc[nt][2] + sB[col], acc[nt][3] + sB[col + 1]);
            }
        }
        __syncthreads();
        // ---- epilogue: 1024 (edge,head) items on 512 threads
        {
            float4 qs0[4], qd0[4], qs1[4], qd1[4];
            if (v0) {
                const float4* ps = (const float4*)(g_q + (size_t)s0 * 128 + h * 16);
                const float4* pd = (const float4*)(g_q + (size_t)d0 * 128 + h * 16);
#pragma unroll
                for (int j = 0; j < 4; j++) { qs0[j] = ps[j]; qd0[j] = pd[j]; }
            }
            if (v1) {
                const float4* ps = (const float4*)(g_q + (size_t)s1 * 128 + h * 16);
                const float4* pd = (const float4*)(g_q + (size_t)d1 * 128 + h * 16);
#pragma unroll
                for (int j = 0; j < 4; j++) { qs1[j] = ps[j]; qd1[j] = pd[j]; }
            }
            if (v0) {
                const float4* kk = (const float4*)(kf + et0 * KPW + h * 16);
                float im = 0.f, om = 0.f, dg = 0.f;
#pragma unroll
                for (int j = 0; j < 4; j++) {
                    float4 a = qs0[j], b = qd0[j], c = kk[j];
                    im += a.x*c.x + a.y*c.y + a.z*c.z + a.w*c.w;
                    om += b.x*c.x + b.y*c.y + b.z*c.z + b.w*c.w;
                    dg += a.x*b.x + a.y*b.y + a.z*b.z + a.w*b.w;
                }
                float ein = __expf(im * SCALE), eou = __expf(om * SCALE), edg = __expf(dg * SCALE);
                size_t o = (size_t)e0 * NHEADS + h;
                g_Ein[o] = ein; g_Eou[o] = eou; g_Edg[o] = edg;
                int idx = d0 * NHEADS + h;
                atomicAdd(&g_D[idx], ein);
                atomicAdd(&g_D[OFFM + idx], eou);
                atomicAdd(&g_D[2 * OFFM + idx], edg);
            }
            if (v1) {
                const float4* kk = (const float4*)(kf + (et0 + 64) * KPW + h * 16);
                float im = 0.f, om = 0.f, dg = 0.f;
#pragma unroll
                for (int j = 0; j < 4; j++) {
                    float4 a = qs1[j], b = qd1[j], c = kk[j];
                    im += a.x*c.x + a.y*c.y + a.z*c.z + a.w*c.w;
                    om += b.x*c.x + b.y*c.y + b.z*c.z + b.w*c.w;
                    dg += a.x*b.x + a.y*b.y + a.z*b.z + a.w*b.w;
                }
                float ein = __expf(im * SCALE), eou = __expf(om * SCALE), edg = __expf(dg * SCALE);
                size_t o = (size_t)e1 * NHEADS + h;
                g_Ein[o] = ein; g_Eou[o] = eou; g_Edg[o] = edg;
                int idx = d1 * NHEADS + h;
                atomicAdd(&g_D[idx], ein);
                atomicAdd(&g_D[OFFM + idx], eou);
                atomicAdd(&g_D[2 * OFFM + idx], edg);
            }
        }
        // no trailing barrier: next tile's load_conv overlaps this epilogue
    }
}

__global__ void __launch_bounds__(512, 1) out_tc_kernel(const float* __restrict__ Wo,
        const float* __restrict__ bo, float* __restrict__ out, int N) {
    extern __shared__ char sm[];
    int tid = threadIdx.x, wid = tid >> 5, lane = tid & 31;
    __nv_bfloat16* WH = (__nv_bfloat16*)(sm + O_WH);
    __nv_bfloat16* WL = (__nv_bfloat16*)(sm + O_WL);
    __nv_bfloat16* AH = (__nv_bfloat16*)(sm + O_AH);
    __nv_bfloat16* AL = (__nv_bfloat16*)(sm + O_AL);
    float* sB = (float*)(sm + O_SB);
    load_conv<512, false>(Wo, 0, 128, WH, WL, tid, nullptr);
    if (tid < 128) sB[tid] = bo[tid];
    __syncthreads();
    int wr = (wid >> 1) << 4, wc = (wid & 1) << 6;
    int qp = (lane & 3) * 2;
    int ntiles = (N + 127) >> 7;
    for (int tile = blockIdx.x; tile < ntiles; tile += gridDim.x) {
        int row0 = tile << 7;
        load_conv<512, true>(g_v, row0, N, AH, AL, tid, g_S);
        __syncthreads();
        float acc[8][4];
        mma_tile(AH, AL, WH, WL, lane, wr, wc, acc);
        {
            int r = wr + (lane >> 2);
            int gr0 = row0 + r, gr1 = gr0 + 8;
#pragma unroll
            for (int nt = 0; nt < 8; nt++) {
                int col = wc + nt * 8 + qp;
                float x0 = acc[nt][0] + sB[col],   x1 = acc[nt][1] + sB[col + 1];
                float x2 = acc[nt][2] + sB[col],   x3 = acc[nt][3] + sB[col + 1];
                x0 = (x0 > 0.f) ? x0 : 0.1f * x0;  x1 = (x1 > 0.f) ? x1 : 0.1f * x1;
                x2 = (x2 > 0.f) ? x2 : 0.1f * x2;  x3 = (x3 > 0.f) ? x3 : 0.1f * x3;
                if (gr0 < N) *(float2*)(out + (size_t)gr0 * 128 + col) = make_float2(x0, x1);
                if (gr1 < N) *(float2*)(out + (size_t)gr1 * 128 + col) = make_float2(x2, x3);
            }
        }
        __syncthreads();
    }
}

__global__ void init_kernel(const float* __restrict__ dist,
                            const float* __restrict__ lam, int E) {
    int t = blockIdx.x * blockDim.x + threadIdx.x;
    if (t < 3 * OFFM) g_D[t] = 0.f;
    if (t < OFFM) g_S[t] = 0.f;
    if (t < E) g_att[t] = __powf(dist[t], lam[0]);
}

__global__ void recip_kernel(int N) {
    int t = blockIdx.x * blockDim.x + threadIdx.x;
    if (t >= N * NHEADS) return;
#pragma unroll
    for (int k = 0; k < 3; k++) {
        float d = g_D[k * OFFM + t];
        g_Di[k * OFFM + t] = (d != 0.f) ? 1.f / d : 0.f;
    }
}

__global__ void score_kernel(const int* __restrict__ dst, int E) {
    int t = blockIdx.x * blockDim.x + threadIdx.x;
    if (t >= E * NHEADS) return;
    int e = t >> 3, h = t & 7;
    int idx = dst[e] * NHEADS + h;
    float s = g_Ein[t] * g_Di[idx]
            + g_Eou[t] * g_Di[OFFM + idx]
            + g_Edg[t] * g_Di[2 * OFFM + idx];
    atomicAdd(&g_S[idx], s * g_att[e]);
}

// ---------------- launch -----------------------------------------------------
extern "C" void kernel_launch(void* const* d_in, const int* in_sizes, int n_in,
                              void* d_out, int out_size) {
    const float* node_h   = (const float*)d_in[0];
    const float* edge_h   = (const float*)d_in[1];
    const float* distance = (const float*)d_in[2];
    const float* Wq = (const float*)d_in[3];  const float* bq = (const float*)d_in[4];
    const float* Wk = (const float*)d_in[5];  const float* bk = (const float*)d_in[6];
    const float* Wv = (const float*)d_in[7];  const float* bv = (const float*)d_in[8];
    const float* Wo = (const float*)d_in[9];  const float* bo = (const float*)d_in[10];
    const float* lam = (const float*)d_in[11];
    const int*   src = (const int*)d_in[12];
    const int*   dst = (const int*)d_in[13];

    int N = in_sizes[0] / F;
    int E = in_sizes[12];
    float* out = (float*)d_out;

    cudaFuncSetAttribute(qv_tc_kernel, cudaFuncAttributeMaxDynamicSharedMemorySize, QV_SMEM);
    cudaFuncSetAttribute(k_logits_tc_kernel, cudaFuncAttributeMaxDynamicSharedMemorySize, K_SMEM);
    cudaFuncSetAttribute(out_tc_kernel, cudaFuncAttributeMaxDynamicSharedMemorySize, O_SMEM);

    int ib = (3 * OFFM + 255) / 256;
    init_kernel<<<ib, 256>>>(distance, lam, E);

    qv_tc_kernel<<<PGRID, 512, QV_SMEM>>>(node_h, Wq, bq, Wv, bv, N);

    k_logits_tc_kernel<<<PGRID, 512, K_SMEM>>>(edge_h, Wk, bk, src, dst, E);

    int tb = (E * NHEADS + 255) / 256;
    int db = (N * NHEADS + 255) / 256;
    recip_kernel<<<db, 256>>>(N);
    score_kernel<<<tb, 256>>>(dst, E);

    out_tc_kernel<<<PGRID, 512, O_SMEM>>>(Wo, bo, out, N);
}

// round 15
// speedup vs baseline: 1.5188x; 1.1084x over previous
#include <cuda_runtime.h>
#include <cuda_bf16.h>
#include <math.h>

#define F 128
#define NHEADS 8
#define SCALE 0.25f            // 1/sqrt(16)
#define MAXN 50048
#define MAXE 640064
#define OFFM (MAXN*NHEADS)
#define PGRID 152               // persistent, 1 CTA/SM

// ---------------- device scratch (static: no allocations allowed) ----------
__device__ float g_q  [MAXN*F];
__device__ float g_v  [MAXN*F];
__device__ float g_Ein[MAXE*NHEADS];
__device__ float g_Eou[MAXE*NHEADS];
__device__ float g_Edg[MAXE*NHEADS];
__device__ float g_att[MAXE];
__device__ float g_D  [3*OFFM];
__device__ float g_Di [3*OFFM];
__device__ float g_S  [OFFM];

// ---------------- helpers ---------------------------------------------------
__device__ __forceinline__ unsigned pack_bf2(float flo, float fhi) {
    unsigned r;
    asm("cvt.rn.satfinite.bf16x2.f32 %0, %1, %2;" : "=r"(r) : "f"(fhi), "f"(flo));
    return r;
}
__device__ __forceinline__ void mma_bf16(float (&c)[4], const unsigned (&a)[4],
                                         const unsigned (&b)[2]) {
    asm volatile("mma.sync.aligned.m16n8k16.row.col.f32.bf16.bf16.f32 "
        "{%0,%1,%2,%3}, {%4,%5,%6,%7}, {%8,%9}, {%0,%1,%2,%3};"
        : "+f"(c[0]), "+f"(c[1]), "+f"(c[2]), "+f"(c[3])
        : "r"(a[0]), "r"(a[1]), "r"(a[2]), "r"(a[3]), "r"(b[0]), "r"(b[1]));
}
__device__ __forceinline__ void barx(int id, int cnt) {
    asm volatile("bar.sync %0, %1;" :: "r"(id), "r"(cnt) : "memory");
}

#define SAW 136
#define TB  (128*SAW*2)          // bytes per 128x128 bf16 tile (34816)
#define KPW 132                  // fp32 k-tile row stride (floats)

template<int NT, bool SCALED>
__device__ __forceinline__ void load_conv(const float* __restrict__ src, int row0, int nrows,
                                          __nv_bfloat16* aHi, __nv_bfloat16* aLo,
                                          int tid, const float* __restrict__ scl) {
    for (int g = tid; g < 2048; g += NT) {
        int row = g >> 4, c8 = (g & 15) << 3;
        float fs[8] = {0.f, 0.f, 0.f, 0.f, 0.f, 0.f, 0.f, 0.f};
        int gr = row0 + row;
        if (gr < nrows) {
            const float4* p = (const float4*)(src + (size_t)gr * 128 + c8);
            float4 f0 = p[0], f1 = p[1];
            fs[0] = f0.x; fs[1] = f0.y; fs[2] = f0.z; fs[3] = f0.w;
            fs[4] = f1.x; fs[5] = f1.y; fs[6] = f1.z; fs[7] = f1.w;
            if (SCALED) {
                float sc = scl[gr * NHEADS + (c8 >> 4)];
#pragma unroll
                for (int j = 0; j < 8; j++) fs[j] *= sc;
            }
        }
        unsigned hi[4], lo[4];
#pragma unroll
        for (int j = 0; j < 4; j++) {
            unsigned h = pack_bf2(fs[2 * j], fs[2 * j + 1]);
            float h0f = __uint_as_float(h << 16);
            float h1f = __uint_as_float(h & 0xFFFF0000u);
            hi[j] = h;
            lo[j] = pack_bf2(fs[2 * j] - h0f, fs[2 * j + 1] - h1f);
        }
        *(uint4*)(aHi + row * SAW + c8) = make_uint4(hi[0], hi[1], hi[2], hi[3]);
        *(uint4*)(aLo + row * SAW + c8) = make_uint4(lo[0], lo[1], lo[2], lo[3]);
    }
}

// 16-warp variant (qv/out): one warp's 16x64 share (R8-validated)
__device__ __forceinline__ void mma_tile(const __nv_bfloat16* aH, const __nv_bfloat16* aL,
                                         const __nv_bfloat16* wH, const __nv_bfloat16* wL,
                                         int lane, int wr, int wc, float (&acc)[8][4]) {
    int qp = (lane & 3) * 2;
    int r0 = wr + (lane >> 2);
#pragma unroll
    for (int nt = 0; nt < 8; nt++)
#pragma unroll
        for (int c = 0; c < 4; c++) acc[nt][c] = 0.f;
#pragma unroll
    for (int ks = 0; ks < 8; ks++) {
        int kc = ks * 16 + qp;
        unsigned aHf[4], aLf[4];
        aHf[0] = *(const unsigned*)(aH + r0 * SAW + kc);
        aHf[1] = *(const unsigned*)(aH + (r0 + 8) * SAW + kc);
        aHf[2] = *(const unsigned*)(aH + r0 * SAW + kc + 8);
        aHf[3] = *(const unsigned*)(aH + (r0 + 8) * SAW + kc + 8);
        aLf[0] = *(const unsigned*)(aL + r0 * SAW + kc);
        aLf[1] = *(const unsigned*)(aL + (r0 + 8) * SAW + kc);
        aLf[2] = *(const unsigned*)(aL + r0 * SAW + kc + 8);
        aLf[3] = *(const unsigned*)(aL + (r0 + 8) * SAW + kc + 8);
#pragma unroll
        for (int nt = 0; nt < 8; nt++) {
            int n = wc + nt * 8 + (lane >> 2);
            unsigned bHf[2], bLf[2];
            bHf[0] = *(const unsigned*)(wH + n * SAW + kc);
            bHf[1] = *(const unsigned*)(wH + n * SAW + kc + 8);
            bLf[0] = *(const unsigned*)(wL + n * SAW + kc);
            bLf[1] = *(const unsigned*)(wL + n * SAW + kc + 8);
            mma_bf16(acc[nt], aHf, bHf);
            mma_bf16(acc[nt], aHf, bLf);
            mma_bf16(acc[nt], aLf, bHf);
        }
    }
}

// ---------------- smem layouts (byte offsets) -------------------------------
#define K_WH 0
#define K_WL TB
#define K_AH (2*TB)
#define K_AL (3*TB)
#define K_KF (4*TB)
#define K_SB (K_KF + 128*KPW*4)
#define K_SMEM (K_SB + 512)
#define QV_WQH 0
#define QV_WQL TB
#define QV_WVH (2*TB)
#define QV_WVL (3*TB)
#define QV_AH  (4*TB)
#define QV_AL  (5*TB)
#define QV_SBQ (6*TB)
#define QV_SBV (QV_SBQ + 512)
#define QV_SMEM (QV_SBV + 512)
#define O_WH 0
#define O_WL TB
#define O_AH (2*TB)
#define O_AL (3*TB)
#define O_SB (4*TB)
#define O_SMEM (O_SB + 512)

// ---------------- kernels ---------------------------------------------------

__global__ void __launch_bounds__(512, 1) qv_tc_kernel(const float* __restrict__ node_h,
        const float* __restrict__ Wq, const float* __restrict__ bq,
        const float* __restrict__ Wv, const float* __restrict__ bv, int N) {
    extern __shared__ char sm[];
    int tid = threadIdx.x, wid = tid >> 5, lane = tid & 31;
    __nv_bfloat16* WqH = (__nv_bfloat16*)(sm + QV_WQH);
    __nv_bfloat16* WqL = (__nv_bfloat16*)(sm + QV_WQL);
    __nv_bfloat16* WvH = (__nv_bfloat16*)(sm + QV_WVH);
    __nv_bfloat16* WvL = (__nv_bfloat16*)(sm + QV_WVL);
    __nv_bfloat16* AH  = (__nv_bfloat16*)(sm + QV_AH);
    __nv_bfloat16* AL  = (__nv_bfloat16*)(sm + QV_AL);
    float* sBq = (float*)(sm + QV_SBQ);
    float* sBv = (float*)(sm + QV_SBV);
    load_conv<512, false>(Wq, 0, 128, WqH, WqL, tid, nullptr);
    load_conv<512, false>(Wv, 0, 128, WvH, WvL, tid, nullptr);
    if (tid < 128) { sBq[tid] = bq[tid]; sBv[tid] = bv[tid]; }
    __syncthreads();
    int wr = (wid >> 1) << 4, wc = (wid & 1) << 6;
    int qp = (lane & 3) * 2;
    int ntiles = (N + 127) >> 7;
    for (int tile = blockIdx.x; tile < ntiles; tile += gridDim.x) {
        int row0 = tile << 7;
        load_conv<512, false>(node_h, row0, N, AH, AL, tid, nullptr);
        __syncthreads();
        float acc[8][4];
        mma_tile(AH, AL, WqH, WqL, lane, wr, wc, acc);
        {
            int r = wr + (lane >> 2);
            int gr0 = row0 + r, gr1 = gr0 + 8;
#pragma unroll
            for (int nt = 0; nt < 8; nt++) {
                int col = wc + nt * 8 + qp;
                if (gr0 < N) *(float2*)(g_q + (size_t)gr0 * 128 + col) =
                    make_float2(acc[nt][0] + sBq[col], acc[nt][1] + sBq[col + 1]);
                if (gr1 < N) *(float2*)(g_q + (size_t)gr1 * 128 + col) =
                    make_float2(acc[nt][2] + sBq[col], acc[nt][3] + sBq[col + 1]);
            }
        }
        mma_tile(AH, AL, WvH, WvL, lane, wr, wc, acc);
        {
            int r = wr + (lane >> 2);
            int gr0 = row0 + r, gr1 = gr0 + 8;
#pragma unroll
            for (int nt = 0; nt < 8; nt++) {
                int col = wc + nt * 8 + qp;
                if (gr0 < N) *(float2*)(g_v + (size_t)gr0 * 128 + col) =
                    make_float2(acc[nt][0] + sBv[col], acc[nt][1] + sBv[col + 1]);
                if (gr1 < N) *(float2*)(g_v + (size_t)gr1 * 128 + col) =
                    make_float2(acc[nt][2] + sBv[col], acc[nt][3] + sBv[col + 1]);
            }
        }
        __syncthreads();
    }
}

// warp-specialized: warps 0-7 = GEMM+A-load producers, warps 8-15 = epilogue
// consumers. Named barriers: 1 = kf full (512), 2 = kf empty (512),
// 3 = A-tile ready (GEMM group, 256).
__global__ void __launch_bounds__(512, 1) k_logits_tc_kernel(const float* __restrict__ edge_h,
        const float* __restrict__ Wk, const float* __restrict__ bk,
        const int* __restrict__ src, const int* __restrict__ dst, int E) {
    extern __shared__ char sm[];
    int tid = threadIdx.x, wid = tid >> 5, lane = tid & 31;
    __nv_bfloat16* WH = (__nv_bfloat16*)(sm + K_WH);
    __nv_bfloat16* WL = (__nv_bfloat16*)(sm + K_WL);
    __nv_bfloat16* AH = (__nv_bfloat16*)(sm + K_AH);
    __nv_bfloat16* AL = (__nv_bfloat16*)(sm + K_AL);
    float* kf = (float*)(sm + K_KF);
    float* sB = (float*)(sm + K_SB);
    load_conv<512, false>(Wk, 0, 128, WH, WL, tid, nullptr);
    if (tid < 128) sB[tid] = bk[tid];
    __syncthreads();
    int ntiles = (E + 127) >> 7;

    if (wid < 8) {
        // ---------------- GEMM / producer warps (256 threads) ----------------
        int wr = wid << 4;                 // rows [wr, wr+16)
        int qp = (lane & 3) * 2;
        int r0 = wr + (lane >> 2);
        for (int tile = blockIdx.x; tile < ntiles; tile += gridDim.x) {
            int row0 = tile << 7;
            load_conv<256, false>(edge_h, row0, E, AH, AL, tid, nullptr);
            barx(3, 256);                  // A tile ready (GEMM group)
            float acc[16][4];
#pragma unroll
            for (int nt = 0; nt < 16; nt++)
#pragma unroll
                for (int c = 0; c < 4; c++) acc[nt][c] = 0.f;
#pragma unroll
            for (int ks = 0; ks < 8; ks++) {
                int kc = ks * 16 + qp;
                unsigned aHf[4], aLf[4];
                aHf[0] = *(const unsigned*)(AH + r0 * SAW + kc);
                aHf[1] = *(const unsigned*)(AH + (r0 + 8) * SAW + kc);
                aHf[2] = *(const unsigned*)(AH + r0 * SAW + kc + 8);
                aHf[3] = *(const unsigned*)(AH + (r0 + 8) * SAW + kc + 8);
                aLf[0] = *(const unsigned*)(AL + r0 * SAW + kc);
                aLf[1] = *(const unsigned*)(AL + (r0 + 8) * SAW + kc);
                aLf[2] = *(const unsigned*)(AL + r0 * SAW + kc + 8);
                aLf[3] = *(const unsigned*)(AL + (r0 + 8) * SAW + kc + 8);
#pragma unroll
                for (int nt = 0; nt < 16; nt++) {
                    int n = nt * 8 + (lane >> 2);
                    unsigned bHf[2], bLf[2];
                    bHf[0] = *(const unsigned*)(WH + n * SAW + kc);
                    bHf[1] = *(const unsigned*)(WH + n * SAW + kc + 8);
                    bLf[0] = *(const unsigned*)(WL + n * SAW + kc);
                    bLf[1] = *(const unsigned*)(WL + n * SAW + kc + 8);
                    mma_bf16(acc[nt], aHf, bHf);
                    mma_bf16(acc[nt], aHf, bLf);
                    mma_bf16(acc[nt], aLf, bHf);
                }
            }
            barx(2, 512);                  // wait: kf consumed (prev tile)
#pragma unroll
            for (int nt = 0; nt < 16; nt++) {
                int col = nt * 8 + qp;
                *(float2*)(kf + r0 * KPW + col) =
                    make_float2(acc[nt][0] + sB[col], acc[nt][1] + sB[col + 1]);
                *(float2*)(kf + (r0 + 8) * KPW + col) =
                    make_float2(acc[nt][2] + sB[col], acc[nt][3] + sB[col + 1]);
            }
            barx(1, 512);                  // kf full
        }
    } else {
        // ---------------- epilogue / consumer warps (256 threads) ------------
        int j  = tid - 256;                // 0..255
        int h  = j & 7;
        int eb = j >> 3;                   // 0..31
        for (int tile = blockIdx.x; tile < ntiles; tile += gridDim.x) {
            int row0 = tile << 7;
            // preload this tile's indices (overlaps producer MMA)
            int ee[4]; int ss[4], dd[4]; bool vv[4];
#pragma unroll
            for (int i = 0; i < 4; i++) {
                ee[i] = row0 + eb + 32 * i;
                vv[i] = ee[i] < E;
                ss[i] = 0; dd[i] = 0;
                if (vv[i]) { ss[i] = __ldg(src + ee[i]); dd[i] = __ldg(dst + ee[i]); }
            }
            barx(2, 512);                  // signal: kf free (prev epilogue done)
            barx(1, 512);                  // wait: kf full
#pragma unroll
            for (int i = 0; i < 4; i++) {
                if (!vv[i]) continue;
                int et = eb + 32 * i;
                const float4* ps = (const float4*)(g_q + (size_t)ss[i] * 128 + h * 16);
                const float4* pd = (const float4*)(g_q + (size_t)dd[i] * 128 + h * 16);
                const float4* kk = (const float4*)(kf + et * KPW + h * 16);
                float4 qs[4], qd[4];
#pragma unroll
                for (int t = 0; t < 4; t++) { qs[t] = ps[t]; qd[t] = pd[t]; }
                float im = 0.f, om = 0.f, dg = 0.f;
#pragma unroll
                for (int t = 0; t < 4; t++) {
                    float4 a = qs[t], b = qd[t], c = kk[t];
                    im += a.x*c.x + a.y*c.y + a.z*c.z + a.w*c.w;
                    om += b.x*c.x + b.y*c.y + b.z*c.z + b.w*c.w;
                    dg += a.x*b.x + a.y*b.y + a.z*b.z + a.w*b.w;
                }
                float ein = __expf(im * SCALE), eou = __expf(om * SCALE), edg = __expf(dg * SCALE);
                size_t o = (size_t)ee[i] * NHEADS + h;
                g_Ein[o] = ein; g_Eou[o] = eou; g_Edg[o] = edg;
                int idx = dd[i] * NHEADS + h;
                atomicAdd(&g_D[idx], ein);
                atomicAdd(&g_D[OFFM + idx], eou);
                atomicAdd(&g_D[2 * OFFM + idx], edg);
            }
        }
    }
}

__global__ void __launch_bounds__(512, 1) out_tc_kernel(const float* __restrict__ Wo,
        const float* __restrict__ bo, float* __restrict__ out, int N) {
    extern __shared__ char sm[];
    int tid = threadIdx.x, wid = tid >> 5, lane = tid & 31;
    __nv_bfloat16* WH = (__nv_bfloat16*)(sm + O_WH);
    __nv_bfloat16* WL = (__nv_bfloat16*)(sm + O_WL);
    __nv_bfloat16* AH = (__nv_bfloat16*)(sm + O_AH);
    __nv_bfloat16* AL = (__nv_bfloat16*)(sm + O_AL);
    float* sB = (float*)(sm + O_SB);
    load_conv<512, false>(Wo, 0, 128, WH, WL, tid, nullptr);
    if (tid < 128) sB[tid] = bo[tid];
    __syncthreads();
    int wr = (wid >> 1) << 4, wc = (wid & 1) << 6;
    int qp = (lane & 3) * 2;
    int ntiles = (N + 127) >> 7;
    for (int tile = blockIdx.x; tile < ntiles; tile += gridDim.x) {
        int row0 = tile << 7;
        load_conv<512, true>(g_v, row0, N, AH, AL, tid, g_S);
        __syncthreads();
        float acc[8][4];
        mma_tile(AH, AL, WH, WL, lane, wr, wc, acc);
        {
            int r = wr + (lane >> 2);
            int gr0 = row0 + r, gr1 = gr0 + 8;
#pragma unroll
            for (int nt = 0; nt < 8; nt++) {
                int col = wc + nt * 8 + qp;
                float x0 = acc[nt][0] + sB[col],   x1 = acc[nt][1] + sB[col + 1];
                float x2 = acc[nt][2] + sB[col],   x3 = acc[nt][3] + sB[col + 1];
                x0 = (x0 > 0.f) ? x0 : 0.1f * x0;  x1 = (x1 > 0.f) ? x1 : 0.1f * x1;
                x2 = (x2 > 0.f) ? x2 : 0.1f * x2;  x3 = (x3 > 0.f) ? x3 : 0.1f * x3;
                if (gr0 < N) *(float2*)(out + (size_t)gr0 * 128 + col) = make_float2(x0, x1);
                if (gr1 < N) *(float2*)(out + (size_t)gr1 * 128 + col) = make_float2(x2, x3);
            }
        }
        __syncthreads();
    }
}

__global__ void init_d_kernel(int n) {
    int t = blockIdx.x * blockDim.x + threadIdx.x;
    if (t < 3 * OFFM) g_D[t] = 0.f;
    if (t < OFFM) g_S[t] = 0.f;
}

__global__ void init_att_kernel(const float* __restrict__ dist,
                                const float* __restrict__ lam, int E) {
    int t = blockIdx.x * blockDim.x + threadIdx.x;
    if (t < E) g_att[t] = __powf(dist[t], lam[0]);
}

__global__ void recip_kernel(int N) {
    int t = blockIdx.x * blockDim.x + threadIdx.x;
    if (t >= N * NHEADS) return;
#pragma unroll
    for (int k = 0; k < 3; k++) {
        float d = g_D[k * OFFM + t];
        g_Di[k * OFFM + t] = (d != 0.f) ? 1.f / d : 0.f;
    }
}

__global__ void score_kernel(const int* __restrict__ dst, int E) {
    int t = blockIdx.x * blockDim.x + threadIdx.x;
    if (t >= E * NHEADS) return;
    int e = t >> 3, h = t & 7;
    int idx = dst[e] * NHEADS + h;
    float s = g_Ein[t] * g_Di[idx]
            + g_Eou[t] * g_Di[OFFM + idx]
            + g_Edg[t] * g_Di[2 * OFFM + idx];
    atomicAdd(&g_S[idx], s * g_att[e]);
}

// ---------------- launch -----------------------------------------------------
extern "C" void kernel_launch(void* const* d_in, const int* in_sizes, int n_in,
                              void* d_out, int out_size) {
    const float* node_h   = (const float*)d_in[0];
    const float* edge_h   = (const float*)d_in[1];
    const float* distance = (const float*)d_in[2];
    const float* Wq = (const float*)d_in[3];  const float* bq = (const float*)d_in[4];
    const float* Wk = (const float*)d_in[5];  const float* bk = (const float*)d_in[6];
    const float* Wv = (const float*)d_in[7];  const float* bv = (const float*)d_in[8];
    const float* Wo = (const float*)d_in[9];  const float* bo = (const float*)d_in[10];
    const float* lam = (const float*)d_in[11];
    const int*   src = (const int*)d_in[12];
    const int*   dst = (const int*)d_in[13];

    int N = in_sizes[0] / F;
    int E = in_sizes[12];
    float* out = (float*)d_out;

    cudaFuncSetAttribute(qv_tc_kernel, cudaFuncAttributeMaxDynamicSharedMemorySize, QV_SMEM);
    cudaFuncSetAttribute(k_logits_tc_kernel, cudaFuncAttributeMaxDynamicSharedMemorySize, K_SMEM);
    cudaFuncSetAttribute(out_tc_kernel, cudaFuncAttributeMaxDynamicSharedMemorySize, O_SMEM);

    // launch order puts k_logits 4th (the slot ncu captures)
    int ib = (3 * OFFM + 255) / 256;
    init_d_kernel<<<ib, 256>>>(0);
    init_att_kernel<<<(E + 255) / 256, 256>>>(distance, lam, E);

    qv_tc_kernel<<<PGRID, 512, QV_SMEM>>>(node_h, Wq, bq, Wv, bv, N);

    k_logits_tc_kernel<<<PGRID, 512, K_SMEM>>>(edge_h, Wk, bk, src, dst, E);

    int tb = (E * NHEADS + 255) / 256;
    int db = (N * NHEADS + 255) / 256;
    recip_kernel<<<db, 256>>>(N);
    score_kernel<<<tb, 256>>>(dst, E);

    out_tc_kernel<<<PGRID, 512, O_SMEM>>>(Wo, bo, out, N);
}

// round 16
// speedup vs baseline: 1.5226x; 1.0025x over previous
#include <cuda_runtime.h>
#include <cuda_bf16.h>
#include <math.h>

#define F 128
#define NHEADS 8
#define SCALE 0.25f            // 1/sqrt(16)
#define MAXN 50048
#define MAXE 640064
#define OFFM (MAXN*NHEADS)
#define PGRID 152               // persistent, 1 CTA/SM

// ---------------- device scratch (static: no allocations allowed) ----------
__device__ float g_q  [MAXN*F];
__device__ float g_v  [MAXN*F];
__device__ float g_Ein[MAXE*NHEADS];
__device__ float g_Eou[MAXE*NHEADS];
__device__ float g_Edg[MAXE*NHEADS];
__device__ float g_att[MAXE];
__device__ float g_D  [3*OFFM];
__device__ float g_Di [3*OFFM];
__device__ float g_S  [OFFM];

// ---------------- helpers ---------------------------------------------------
__device__ __forceinline__ unsigned pack_bf2(float flo, float fhi) {
    unsigned r;
    asm("cvt.rn.satfinite.bf16x2.f32 %0, %1, %2;" : "=r"(r) : "f"(fhi), "f"(flo));
    return r;
}
__device__ __forceinline__ void mma_bf16(float (&c)[4], const unsigned (&a)[4],
                                         const unsigned (&b)[2]) {
    asm volatile("mma.sync.aligned.m16n8k16.row.col.f32.bf16.bf16.f32 "
        "{%0,%1,%2,%3}, {%4,%5,%6,%7}, {%8,%9}, {%0,%1,%2,%3};"
        : "+f"(c[0]), "+f"(c[1]), "+f"(c[2]), "+f"(c[3])
        : "r"(a[0]), "r"(a[1]), "r"(a[2]), "r"(a[3]), "r"(b[0]), "r"(b[1]));
}
__device__ __forceinline__ void barx(int id, int cnt) {
    asm volatile("bar.sync %0, %1;" :: "r"(id), "r"(cnt) : "memory");
}

#define SAW 136
#define TB  (128*SAW*2)          // bytes per 128x128 bf16 tile (34816)
#define KPW 132                  // fp32 k-tile row stride (floats)

template<int NT, bool SCALED>
__device__ __forceinline__ void load_conv(const float* __restrict__ src, int row0, int nrows,
                                          __nv_bfloat16* aHi, __nv_bfloat16* aLo,
                                          int tid, const float* __restrict__ scl) {
    for (int g = tid; g < 2048; g += NT) {
        int row = g >> 4, c8 = (g & 15) << 3;
        float fs[8] = {0.f, 0.f, 0.f, 0.f, 0.f, 0.f, 0.f, 0.f};
        int gr = row0 + row;
        if (gr < nrows) {
            const float4* p = (const float4*)(src + (size_t)gr * 128 + c8);
            float4 f0 = p[0], f1 = p[1];
            fs[0] = f0.x; fs[1] = f0.y; fs[2] = f0.z; fs[3] = f0.w;
            fs[4] = f1.x; fs[5] = f1.y; fs[6] = f1.z; fs[7] = f1.w;
            if (SCALED) {
                float sc = scl[gr * NHEADS + (c8 >> 4)];
#pragma unroll
                for (int j = 0; j < 8; j++) fs[j] *= sc;
            }
        }
        unsigned hi[4], lo[4];
#pragma unroll
        for (int j = 0; j < 4; j++) {
            unsigned h = pack_bf2(fs[2 * j], fs[2 * j + 1]);
            float h0f = __uint_as_float(h << 16);
            float h1f = __uint_as_float(h & 0xFFFF0000u);
            hi[j] = h;
            lo[j] = pack_bf2(fs[2 * j] - h0f, fs[2 * j + 1] - h1f);
        }
        *(uint4*)(aHi + row * SAW + c8) = make_uint4(hi[0], hi[1], hi[2], hi[3]);
        *(uint4*)(aLo + row * SAW + c8) = make_uint4(lo[0], lo[1], lo[2], lo[3]);
    }
}

// 16-warp variant (qv/out): one warp's 16x64 share (R8-validated)
__device__ __forceinline__ void mma_tile(const __nv_bfloat16* aH, const __nv_bfloat16* aL,
                                         const __nv_bfloat16* wH, const __nv_bfloat16* wL,
                                         int lane, int wr, int wc, float (&acc)[8][4]) {
    int qp = (lane & 3) * 2;
    int r0 = wr + (lane >> 2);
#pragma unroll
    for (int nt = 0; nt < 8; nt++)
#pragma unroll
        for (int c = 0; c < 4; c++) acc[nt][c] = 0.f;
#pragma unroll
    for (int ks = 0; ks < 8; ks++) {
        int kc = ks * 16 + qp;
        unsigned aHf[4], aLf[4];
        aHf[0] = *(const unsigned*)(aH + r0 * SAW + kc);
        aHf[1] = *(const unsigned*)(aH + (r0 + 8) * SAW + kc);
        aHf[2] = *(const unsigned*)(aH + r0 * SAW + kc + 8);
        aHf[3] = *(const unsigned*)(aH + (r0 + 8) * SAW + kc + 8);
        aLf[0] = *(const unsigned*)(aL + r0 * SAW + kc);
        aLf[1] = *(const unsigned*)(aL + (r0 + 8) * SAW + kc);
        aLf[2] = *(const unsigned*)(aL + r0 * SAW + kc + 8);
        aLf[3] = *(const unsigned*)(aL + (r0 + 8) * SAW + kc + 8);
#pragma unroll
        for (int nt = 0; nt < 8; nt++) {
            int n = wc + nt * 8 + (lane >> 2);
            unsigned bHf[2], bLf[2];
            bHf[0] = *(const unsigned*)(wH + n * SAW + kc);
            bHf[1] = *(const unsigned*)(wH + n * SAW + kc + 8);
            bLf[0] = *(const unsigned*)(wL + n * SAW + kc);
            bLf[1] = *(const unsigned*)(wL + n * SAW + kc + 8);
            mma_bf16(acc[nt], aHf, bHf);
            mma_bf16(acc[nt], aHf, bLf);
            mma_bf16(acc[nt], aLf, bHf);
        }
    }
}

// ---------------- smem layouts (byte offsets) -------------------------------
#define K_WH 0
#define K_WL TB
#define K_AH (2*TB)
#define K_AL (3*TB)
#define K_KF (4*TB)
#define K_SB (K_KF + 128*KPW*4)
#define K_SMEM (K_SB + 512)
#define QV_WQH 0
#define QV_WQL TB
#define QV_WVH (2*TB)
#define QV_WVL (3*TB)
#define QV_AH  (4*TB)
#define QV_AL  (5*TB)
#define QV_SBQ (6*TB)
#define QV_SBV (QV_SBQ + 512)
#define QV_SMEM (QV_SBV + 512)
#define O_WH 0
#define O_WL TB
#define O_AH (2*TB)
#define O_AL (3*TB)
#define O_SB (4*TB)
#define O_SMEM (O_SB + 512)

// ---------------- kernels ---------------------------------------------------

__global__ void __launch_bounds__(512, 1) qv_tc_kernel(const float* __restrict__ node_h,
        const float* __restrict__ Wq, const float* __restrict__ bq,
        const float* __restrict__ Wv, const float* __restrict__ bv, int N) {
    extern __shared__ char sm[];
    int tid = threadIdx.x, wid = tid >> 5, lane = tid & 31;
    __nv_bfloat16* WqH = (__nv_bfloat16*)(sm + QV_WQH);
    __nv_bfloat16* WqL = (__nv_bfloat16*)(sm + QV_WQL);
    __nv_bfloat16* WvH = (__nv_bfloat16*)(sm + QV_WVH);
    __nv_bfloat16* WvL = (__nv_bfloat16*)(sm + QV_WVL);
    __nv_bfloat16* AH  = (__nv_bfloat16*)(sm + QV_AH);
    __nv_bfloat16* AL  = (__nv_bfloat16*)(sm + QV_AL);
    float* sBq = (float*)(sm + QV_SBQ);
    float* sBv = (float*)(sm + QV_SBV);
    load_conv<512, false>(Wq, 0, 128, WqH, WqL, tid, nullptr);
    load_conv<512, false>(Wv, 0, 128, WvH, WvL, tid, nullptr);
    if (tid < 128) { sBq[tid] = bq[tid]; sBv[tid] = bv[tid]; }
    __syncthreads();
    int wr = (wid >> 1) << 4, wc = (wid & 1) << 6;
    int qp = (lane & 3) * 2;
    int ntiles = (N + 127) >> 7;
    for (int tile = blockIdx.x; tile < ntiles; tile += gridDim.x) {
        int row0 = tile << 7;
        load_conv<512, false>(node_h, row0, N, AH, AL, tid, nullptr);
        __syncthreads();
        float acc[8][4];
        mma_tile(AH, AL, WqH, WqL, lane, wr, wc, acc);
        {
            int r = wr + (lane >> 2);
            int gr0 = row0 + r, gr1 = gr0 + 8;
#pragma unroll
            for (int nt = 0; nt < 8; nt++) {
                int col = wc + nt * 8 + qp;
                if (gr0 < N) *(float2*)(g_q + (size_t)gr0 * 128 + col) =
                    make_float2(acc[nt][0] + sBq[col], acc[nt][1] + sBq[col + 1]);
                if (gr1 < N) *(float2*)(g_q + (size_t)gr1 * 128 + col) =
                    make_float2(acc[nt][2] + sBq[col], acc[nt][3] + sBq[col + 1]);
            }
        }
        mma_tile(AH, AL, WvH, WvL, lane, wr, wc, acc);
        {
            int r = wr + (lane >> 2);
            int gr0 = row0 + r, gr1 = gr0 + 8;
#pragma unroll
            for (int nt = 0; nt < 8; nt++) {
                int col = wc + nt * 8 + qp;
                if (gr0 < N) *(float2*)(g_v + (size_t)gr0 * 128 + col) =
                    make_float2(acc[nt][0] + sBv[col], acc[nt][1] + sBv[col + 1]);
                if (gr1 < N) *(float2*)(g_v + (size_t)gr1 * 128 + col) =
                    make_float2(acc[nt][2] + sBv[col], acc[nt][3] + sBv[col + 1]);
            }
        }
        __syncthreads();
    }
}

// warp-specialized: warps 0-7 = GEMM+A-load producers (each 32 rows x 64 cols),
// warps 8-15 = epilogue consumers. Named barriers: 1 = kf full (512),
// 2 = kf empty (512), 3 = A-tile ready (GEMM group, 256).
__global__ void __launch_bounds__(512, 1) k_logits_tc_kernel(const float* __restrict__ edge_h,
        const float* __restrict__ Wk, const float* __restrict__ bk,
        const int* __restrict__ src, const int* __restrict__ dst, int E) {
    extern __shared__ char sm[];
    int tid = threadIdx.x, wid = tid >> 5, lane = tid & 31;
    __nv_bfloat16* WH = (__nv_bfloat16*)(sm + K_WH);
    __nv_bfloat16* WL = (__nv_bfloat16*)(sm + K_WL);
    __nv_bfloat16* AH = (__nv_bfloat16*)(sm + K_AH);
    __nv_bfloat16* AL = (__nv_bfloat16*)(sm + K_AL);
    float* kf = (float*)(sm + K_KF);
    float* sB = (float*)(sm + K_SB);
    load_conv<512, false>(Wk, 0, 128, WH, WL, tid, nullptr);
    if (tid < 128) sB[tid] = bk[tid];
    __syncthreads();
    int ntiles = (E + 127) >> 7;

    if (wid < 8) {
        // ------------- GEMM / producer warps: 4 row-groups x 2 col-groups ----
        int wrg = wid >> 1, wcg = wid & 1;
        int qp = (lane & 3) * 2;
        int r0 = wrg * 32 + (lane >> 2);     // rows r0, r0+8 (st0); +16,+24 (st1)
        int nbase = wcg * 64;
        for (int tile = blockIdx.x; tile < ntiles; tile += gridDim.x) {
            int row0 = tile << 7;
            load_conv<256, false>(edge_h, row0, E, AH, AL, tid, nullptr);
            barx(3, 256);                  // A tile ready (GEMM group)
            float acc[2][8][4];
#pragma unroll
            for (int st = 0; st < 2; st++)
#pragma unroll
                for (int nt = 0; nt < 8; nt++)
#pragma unroll
                    for (int c = 0; c < 4; c++) acc[st][nt][c] = 0.f;
#pragma unroll
            for (int ks = 0; ks < 8; ks++) {
                int kc = ks * 16 + qp;
                unsigned aHf[2][4], aLf[2][4];
#pragma unroll
                for (int st = 0; st < 2; st++) {
                    int rr = r0 + st * 16;
                    aHf[st][0] = *(const unsigned*)(AH + rr * SAW + kc);
                    aHf[st][1] = *(const unsigned*)(AH + (rr + 8) * SAW + kc);
                    aHf[st][2] = *(const unsigned*)(AH + rr * SAW + kc + 8);
                    aHf[st][3] = *(const unsigned*)(AH + (rr + 8) * SAW + kc + 8);
                    aLf[st][0] = *(const unsigned*)(AL + rr * SAW + kc);
                    aLf[st][1] = *(const unsigned*)(AL + (rr + 8) * SAW + kc);
                    aLf[st][2] = *(const unsigned*)(AL + rr * SAW + kc + 8);
                    aLf[st][3] = *(const unsigned*)(AL + (rr + 8) * SAW + kc + 8);
                }
#pragma unroll
                for (int nt = 0; nt < 8; nt++) {
                    int n = nbase + nt * 8 + (lane >> 2);
                    unsigned bHf[2], bLf[2];
                    bHf[0] = *(const unsigned*)(WH + n * SAW + kc);
                    bHf[1] = *(const unsigned*)(WH + n * SAW + kc + 8);
                    bLf[0] = *(const unsigned*)(WL + n * SAW + kc);
                    bLf[1] = *(const unsigned*)(WL + n * SAW + kc + 8);
#pragma unroll
                    for (int st = 0; st < 2; st++) {
                        mma_bf16(acc[st][nt], aHf[st], bHf);
                        mma_bf16(acc[st][nt], aHf[st], bLf);
                        mma_bf16(acc[st][nt], aLf[st], bHf);
                    }
                }
            }
            barx(2, 512);                  // wait: kf consumed (prev tile)
#pragma unroll
            for (int st = 0; st < 2; st++) {
                int rr = r0 + st * 16;
#pragma unroll
                for (int nt = 0; nt < 8; nt++) {
                    int col = nbase + nt * 8 + qp;
                    *(float2*)(kf + rr * KPW + col) =
                        make_float2(acc[st][nt][0] + sB[col], acc[st][nt][1] + sB[col + 1]);
                    *(float2*)(kf + (rr + 8) * KPW + col) =
                        make_float2(acc[st][nt][2] + sB[col], acc[st][nt][3] + sB[col + 1]);
                }
            }
            barx(1, 512);                  // kf full
        }
    } else {
        // ---------------- epilogue / consumer warps (256 threads) ------------
        int j  = tid - 256;                // 0..255
        int h  = j & 7;
        int eb = j >> 3;                   // 0..31
        for (int tile = blockIdx.x; tile < ntiles; tile += gridDim.x) {
            int row0 = tile << 7;
            // preload this tile's indices (overlaps producer MMA)
            int ee[4]; int ss[4], dd[4]; bool vv[4];
#pragma unroll
            for (int i = 0; i < 4; i++) {
                ee[i] = row0 + eb + 32 * i;
                vv[i] = ee[i] < E;
                ss[i] = 0; dd[i] = 0;
                if (vv[i]) { ss[i] = __ldg(src + ee[i]); dd[i] = __ldg(dst + ee[i]); }
            }
            barx(2, 512);                  // signal: kf free (prev epilogue done)
            barx(1, 512);                  // wait: kf full
#pragma unroll
            for (int i = 0; i < 4; i++) {
                if (!vv[i]) continue;
                int et = eb + 32 * i;
                const float4* ps = (const float4*)(g_q + (size_t)ss[i] * 128 + h * 16);
                const float4* pd = (const float4*)(g_q + (size_t)dd[i] * 128 + h * 16);
                const float4* kk = (const float4*)(kf + et * KPW + h * 16);
                float4 qs[4], qd[4];
#pragma unroll
                for (int t = 0; t < 4; t++) { qs[t] = ps[t]; qd[t] = pd[t]; }
                float im = 0.f, om = 0.f, dg = 0.f;
#pragma unroll
                for (int t = 0; t < 4; t++) {
                    float4 a = qs[t], b = qd[t], c = kk[t];
                    im += a.x*c.x + a.y*c.y + a.z*c.z + a.w*c.w;
                    om += b.x*c.x + b.y*c.y + b.z*c.z + b.w*c.w;
                    dg += a.x*b.x + a.y*b.y + a.z*b.z + a.w*b.w;
                }
                float ein = __expf(im * SCALE), eou = __expf(om * SCALE), edg = __expf(dg * SCALE);
                size_t o = (size_t)ee[i] * NHEADS + h;
                g_Ein[o] = ein; g_Eou[o] = eou; g_Edg[o] = edg;
                int idx = dd[i] * NHEADS + h;
                atomicAdd(&g_D[idx], ein);
                atomicAdd(&g_D[OFFM + idx], eou);
                atomicAdd(&g_D[2 * OFFM + idx], edg);
            }
        }
    }
}

__global__ void __launch_bounds__(512, 1) out_tc_kernel(const float* __restrict__ Wo,
        const float* __restrict__ bo, float* __restrict__ out, int N) {
    extern __shared__ char sm[];
    int tid = threadIdx.x, wid = tid >> 5, lane = tid & 31;
    __nv_bfloat16* WH = (__nv_bfloat16*)(sm + O_WH);
    __nv_bfloat16* WL = (__nv_bfloat16*)(sm + O_WL);
    __nv_bfloat16* AH = (__nv_bfloat16*)(sm + O_AH);
    __nv_bfloat16* AL = (__nv_bfloat16*)(sm + O_AL);
    float* sB = (float*)(sm + O_SB);
    load_conv<512, false>(Wo, 0, 128, WH, WL, tid, nullptr);
    if (tid < 128) sB[tid] = bo[tid];
    __syncthreads();
    int wr = (wid >> 1) << 4, wc = (wid & 1) << 6;
    int qp = (lane & 3) * 2;
    int ntiles = (N + 127) >> 7;
    for (int tile = blockIdx.x; tile < ntiles; tile += gridDim.x) {
        int row0 = tile << 7;
        load_conv<512, true>(g_v, row0, N, AH, AL, tid, g_S);
        __syncthreads();
        float acc[8][4];
        mma_tile(AH, AL, WH, WL, lane, wr, wc, acc);
        {
            int r = wr + (lane >> 2);
            int gr0 = row0 + r, gr1 = gr0 + 8;
#pragma unroll
            for (int nt = 0; nt < 8; nt++) {
                int col = wc + nt * 8 + qp;
                float x0 = acc[nt][0] + sB[col],   x1 = acc[nt][1] + sB[col + 1];
                float x2 = acc[nt][2] + sB[col],   x3 = acc[nt][3] + sB[col + 1];
                x0 = (x0 > 0.f) ? x0 : 0.1f * x0;  x1 = (x1 > 0.f) ? x1 : 0.1f * x1;
                x2 = (x2 > 0.f) ? x2 : 0.1f * x2;  x3 = (x3 > 0.f) ? x3 : 0.1f * x3;
                if (gr0 < N) *(float2*)(out + (size_t)gr0 * 128 + col) = make_float2(x0, x1);
                if (gr1 < N) *(float2*)(out + (size_t)gr1 * 128 + col) = make_float2(x2, x3);
            }
        }
        __syncthreads();
    }
}

__global__ void init_d_kernel(int n) {
    int t = blockIdx.x * blockDim.x + threadIdx.x;
    if (t < 3 * OFFM) g_D[t] = 0.f;
    if (t < OFFM) g_S[t] = 0.f;
}

__global__ void init_att_kernel(const float* __restrict__ dist,
                                const float* __restrict__ lam, int E) {
    int t = blockIdx.x * blockDim.x + threadIdx.x;
    if (t < E) g_att[t] = __powf(dist[t], lam[0]);
}

__global__ void recip_kernel(int N) {
    int t = blockIdx.x * blockDim.x + threadIdx.x;
    if (t >= N * NHEADS) return;
#pragma unroll
    for (int k = 0; k < 3; k++) {
        float d = g_D[k * OFFM + t];
        g_Di[k * OFFM + t] = (d != 0.f) ? 1.f / d : 0.f;
    }
}

__global__ void score_kernel(const int* __restrict__ dst, int E) {
    int t = blockIdx.x * blockDim.x + threadIdx.x;
    if (t >= E * NHEADS) return;
    int e = t >> 3, h = t & 7;
    int idx = dst[e] * NHEADS + h;
    float s = g_Ein[t] * g_Di[idx]
            + g_Eou[t] * g_Di[OFFM + idx]
            + g_Edg[t] * g_Di[2 * OFFM + idx];
    atomicAdd(&g_S[idx], s * g_att[e]);
}

// ---------------- launch -----------------------------------------------------
extern "C" void kernel_launch(void* const* d_in, const int* in_sizes, int n_in,
                              void* d_out, int out_size) {
    const float* node_h   = (const float*)d_in[0];
    const float* edge_h   = (const float*)d_in[1];
    const float* distance = (const float*)d_in[2];
    const float* Wq = (const float*)d_in[3];  const float* bq = (const float*)d_in[4];
    const float* Wk = (const float*)d_in[5];  const float* bk = (const float*)d_in[6];
    const float* Wv = (const float*)d_in[7];  const float* bv = (const float*)d_in[8];
    const float* Wo = (const float*)d_in[9];  const float* bo = (const float*)d_in[10];
    const float* lam = (const float*)d_in[11];
    const int*   src = (const int*)d_in[12];
    const int*   dst = (const int*)d_in[13];

    int N = in_sizes[0] / F;
    int E = in_sizes[12];
    float* out = (float*)d_out;

    cudaFuncSetAttribute(qv_tc_kernel, cudaFuncAttributeMaxDynamicSharedMemorySize, QV_SMEM);
    cudaFuncSetAttribute(k_logits_tc_kernel, cudaFuncAttributeMaxDynamicSharedMemorySize, K_SMEM);
    cudaFuncSetAttribute(out_tc_kernel, cudaFuncAttributeMaxDynamicSharedMemorySize, O_SMEM);

    // launch order keeps k_logits 4th (the slot ncu captures)
    int ib = (3 * OFFM + 255) / 256;
    init_d_kernel<<<ib, 256>>>(0);
    init_att_kernel<<<(E + 255) / 256, 256>>>(distance, lam, E);

    qv_tc_kernel<<<PGRID, 512, QV_SMEM>>>(node_h, Wq, bq, Wv, bv, N);

    k_logits_tc_kernel<<<PGRID, 512, K_SMEM>>>(edge_h, Wk, bk, src, dst, E);

    int tb = (E * NHEADS + 255) / 256;
    int db = (N * NHEADS + 255) / 256;
    recip_kernel<<<db, 256>>>(N);
    score_kernel<<<tb, 256>>>(dst, E);

    out_tc_kernel<<<PGRID, 512, O_SMEM>>>(Wo, bo, out, N);
}